// round 3
// baseline (speedup 1.0000x reference)
#include <cuda_runtime.h>
#include <cuda_bf16.h>
#include <math.h>

#define BB 32
#define NN 196
#define TT 128
#define DH 512
#define VV 10000

// ---------------- device scratch (static, no allocation) ----------------
__device__ float g_keys[BB * NN * DH];      // 12.8 MB
__device__ float g_wk  [BB * NN * DH];      // 12.8 MB
__device__ float g_xseq[BB * TT * DH];      // 8.4 MB
__device__ float g_Gx  [BB * TT * 4 * DH];  // 33.6 MB (x-part of gates, biases folded)
__device__ float g_gpart[16 * BB * 4 * DH]; // split-K partials
__device__ float g_hall[BB * TT * DH];      // all h_t, row = b*TT+t
__device__ float g_z   [BB * 1024];         // [ctx | h] per batch
__device__ float g_c   [BB * DH];
__device__ float g_hwh [BB * DH];
__device__ float g_sc  [BB * NN];

__device__ __forceinline__ float fast_tanh(float x) {
    float y; asm("tanh.approx.f32 %0, %1;" : "=f"(y) : "f"(x)); return y;
}
__device__ __forceinline__ float sigm(float x) { return 1.f / (1.f + expf(-x)); }

// ---------------- generic SGEMM: C[M,N] = A[M,K] @ B[N,K]^T (+b1[n]+b2[n]) ----------------
// 128x128 tile, BK=8, 256 threads, 8x8 microtile. K % 8 == 0, K,lda,ldb % 4 == 0.
__global__ __launch_bounds__(256) void gemm_nt(
    const float* __restrict__ A, int lda,
    const float* __restrict__ B, int ldb,
    const float* __restrict__ bias1, const float* __restrict__ bias2,
    float* __restrict__ C, int ldc, int M, int N, int K)
{
    __shared__ float As[8][128];
    __shared__ float Bs[8][128];
    const int tid = threadIdx.x;
    const int mBase = blockIdx.y * 128;
    const int nBase = blockIdx.x * 128;
    const int lr = tid >> 1;
    const int lc = (tid & 1) * 4;
    const int ty = tid >> 4;
    const int tx = tid & 15;

    float acc[8][8];
#pragma unroll
    for (int i = 0; i < 8; i++)
#pragma unroll
        for (int j = 0; j < 8; j++) acc[i][j] = 0.f;

    const bool aval = (mBase + lr) < M;
    const bool bval = (nBase + lr) < N;
    const float* Aptr = A + (size_t)(mBase + lr) * lda + lc;
    const float* Bptr = B + (size_t)(nBase + lr) * ldb + lc;

    for (int k0 = 0; k0 < K; k0 += 8) {
        float4 av = make_float4(0.f, 0.f, 0.f, 0.f);
        float4 bv = make_float4(0.f, 0.f, 0.f, 0.f);
        if (aval) av = *(const float4*)(Aptr + k0);
        if (bval) bv = *(const float4*)(Bptr + k0);
        As[lc + 0][lr] = av.x; As[lc + 1][lr] = av.y;
        As[lc + 2][lr] = av.z; As[lc + 3][lr] = av.w;
        Bs[lc + 0][lr] = bv.x; Bs[lc + 1][lr] = bv.y;
        Bs[lc + 2][lr] = bv.z; Bs[lc + 3][lr] = bv.w;
        __syncthreads();
#pragma unroll
        for (int kk = 0; kk < 8; kk++) {
            float a[8], b[8];
            *(float4*)&a[0] = *(const float4*)&As[kk][ty * 8];
            *(float4*)&a[4] = *(const float4*)&As[kk][ty * 8 + 4];
            *(float4*)&b[0] = *(const float4*)&Bs[kk][tx * 8];
            *(float4*)&b[4] = *(const float4*)&Bs[kk][tx * 8 + 4];
#pragma unroll
            for (int i = 0; i < 8; i++)
#pragma unroll
                for (int j = 0; j < 8; j++)
                    acc[i][j] = fmaf(a[i], b[j], acc[i][j]);
        }
        __syncthreads();
    }

#pragma unroll
    for (int i = 0; i < 8; i++) {
        const int gm = mBase + ty * 8 + i;
        if (gm >= M) continue;
#pragma unroll
        for (int j = 0; j < 8; j++) {
            const int gn = nBase + tx * 8 + j;
            if (gn < N) {
                float v = acc[i][j];
                if (bias1) v += bias1[gn];
                if (bias2) v += bias2[gn];
                C[(size_t)gm * ldc + gn] = v;
            }
        }
    }
}

// ---------------- embedding gather: g_xseq[b*TT+t][d] = emb[ids[b,t]][d] ----------------
__global__ void gather_x(const int* __restrict__ ids, const float* __restrict__ emb)
{
    const int i = blockIdx.x * 256 + threadIdx.x;
    if (i < BB * TT * DH) {
        const int d = i & (DH - 1);
        const int bt = i >> 9;
        g_xseq[i] = emb[(size_t)ids[bt] * DH + d];
    }
}

// ---------------- hWh[b][d] = dot(h[b], Wh[d]) ; grid (8, BB) ----------------
__global__ __launch_bounds__(256) void hwh_kernel(const float* __restrict__ Wh)
{
    const int b = blockIdx.y;
    const int warp = threadIdx.x >> 5, lane = threadIdx.x & 31;
    const float4* h4 = (const float4*)(g_z + b * 1024 + 512);
#pragma unroll
    for (int dd = 0; dd < 8; dd++) {
        const int d = blockIdx.x * 64 + warp * 8 + dd;
        const float4* w4 = (const float4*)(Wh + (size_t)d * DH);
        float acc = 0.f;
#pragma unroll
        for (int i = 0; i < 4; i++) {
            float4 w = w4[lane + 32 * i];
            float4 h = h4[lane + 32 * i];
            acc += w.x * h.x + w.y * h.y + w.z * h.z + w.w * h.w;
        }
#pragma unroll
        for (int o = 16; o; o >>= 1) acc += __shfl_xor_sync(0xffffffffu, acc, o);
        if (lane == 0) g_hwh[b * DH + d] = acc;
    }
}

// ---------------- scores[b][n] = sum_d tanh(hwh+wk)*v ; grid (25, BB), warp per n ----------------
__global__ __launch_bounds__(256) void scores_kernel(const float* __restrict__ v)
{
    const int b = blockIdx.y;
    const int warp = threadIdx.x >> 5, lane = threadIdx.x & 31;
    const int n = blockIdx.x * 8 + warp;
    if (n >= NN) return;
    const float4* wk4 = (const float4*)(g_wk + ((size_t)b * NN + n) * DH);
    const float4* hw4 = (const float4*)(g_hwh + b * DH);
    const float4* v4  = (const float4*)v;
    float s = 0.f;
#pragma unroll
    for (int i = 0; i < 4; i++) {
        float4 a = wk4[lane + 32 * i];
        float4 c = hw4[lane + 32 * i];
        float4 w = v4[lane + 32 * i];
        s += fast_tanh(a.x + c.x) * w.x + fast_tanh(a.y + c.y) * w.y +
             fast_tanh(a.z + c.z) * w.z + fast_tanh(a.w + c.w) * w.w;
    }
#pragma unroll
    for (int o = 16; o; o >>= 1) s += __shfl_xor_sync(0xffffffffu, s, o);
    if (lane == 0) g_sc[b * NN + n] = s;
}

// ---------------- softmax over N + ctx = alpha @ keys ; grid BB ----------------
__global__ __launch_bounds__(256) void softctx_kernel()
{
    const int b = blockIdx.x, tid = threadIdx.x;
    const int warp = tid >> 5, lane = tid & 31;
    __shared__ float sc[NN + 4];
    __shared__ float red[8];

    float x = (tid < NN) ? g_sc[b * NN + tid] : -1e30f;
    float m = x;
#pragma unroll
    for (int o = 16; o; o >>= 1) m = fmaxf(m, __shfl_xor_sync(0xffffffffu, m, o));
    if (lane == 0) red[warp] = m;
    __syncthreads();
    if (tid < 8) {
        float t = red[tid];
#pragma unroll
        for (int o = 4; o; o >>= 1) t = fmaxf(t, __shfl_xor_sync(0x000000ffu, t, o));
        if (tid == 0) red[0] = t;
    }
    __syncthreads();
    const float bm = red[0];
    __syncthreads();

    float e = (tid < NN) ? __expf(x - bm) : 0.f;
    float s = e;
#pragma unroll
    for (int o = 16; o; o >>= 1) s += __shfl_xor_sync(0xffffffffu, s, o);
    if (lane == 0) red[warp] = s;
    __syncthreads();
    if (tid < 8) {
        float t = red[tid];
#pragma unroll
        for (int o = 4; o; o >>= 1) t += __shfl_xor_sync(0x000000ffu, t, o);
        if (tid == 0) red[0] = t;
    }
    __syncthreads();
    const float inv = 1.f / red[0];
    if (tid < NN) sc[tid] = e * inv;
    __syncthreads();

#pragma unroll
    for (int u = 0; u < 2; u++) {
        const int d = tid + u * 256;
        const float* Kp = g_keys + (size_t)b * NN * DH + d;
        float a0 = 0.f, a1 = 0.f, a2 = 0.f, a3 = 0.f;
        for (int n = 0; n < NN; n += 4) {   // NN = 196 = 49*4
            a0 += sc[n + 0] * Kp[(size_t)(n + 0) * DH];
            a1 += sc[n + 1] * Kp[(size_t)(n + 1) * DH];
            a2 += sc[n + 2] * Kp[(size_t)(n + 2) * DH];
            a3 += sc[n + 3] * Kp[(size_t)(n + 3) * DH];
        }
        g_z[b * 1024 + d] = (a0 + a1) + (a2 + a3);
    }
}

// ---------------- split-K gates: gpart[ks][b][g] = z[b][koff:koff+64] . W'[g][koff:koff+64] ----------------
// grid (16 n-tiles, 16 k-splits). k<512 -> ctx part (W_ih cols 512+), else h part (W_hh).
__global__ __launch_bounds__(256) void gates_kernel(const float* __restrict__ Wih,
                                                    const float* __restrict__ Whh)
{
    __shared__ float Zs[32][65];
    __shared__ float Ws[128][65];
    const int tid = threadIdx.x;
    const int nBase = blockIdx.x * 128;
    const int ks = blockIdx.y;
    const int koff = ks * 64;
    const float* Wsrc; int ldw, coff;
    if (ks < 8) { Wsrc = Wih; ldw = 1024; coff = 512 + koff; }
    else        { Wsrc = Whh; ldw = 512;  coff = koff - 512; }

    { // load z chunk: 32 x 64
        const int r = tid >> 3, c = (tid & 7) * 8;
        const float* src = g_z + r * 1024 + koff + c;
        float4 v0 = *(const float4*)src;
        float4 v1 = *(const float4*)(src + 4);
        Zs[r][c + 0] = v0.x; Zs[r][c + 1] = v0.y; Zs[r][c + 2] = v0.z; Zs[r][c + 3] = v0.w;
        Zs[r][c + 4] = v1.x; Zs[r][c + 5] = v1.y; Zs[r][c + 6] = v1.z; Zs[r][c + 7] = v1.w;
    }
    { // load W chunk: 128 x 64
        const int r0 = tid >> 2, c = (tid & 3) * 16;
#pragma unroll
        for (int rr = 0; rr < 128; rr += 64) {
            const int r = r0 + rr;
            const float* src = Wsrc + (size_t)(nBase + r) * ldw + coff + c;
#pragma unroll
            for (int j = 0; j < 16; j += 4) {
                float4 v = *(const float4*)(src + j);
                Ws[r][c + j + 0] = v.x; Ws[r][c + j + 1] = v.y;
                Ws[r][c + j + 2] = v.z; Ws[r][c + j + 3] = v.w;
            }
        }
    }
    __syncthreads();

    const int ty = tid >> 5, tx = tid & 31;   // 4 b-rows, 4 g-cols (stride 32)
    float acc[4][4];
#pragma unroll
    for (int i = 0; i < 4; i++)
#pragma unroll
        for (int j = 0; j < 4; j++) acc[i][j] = 0.f;

#pragma unroll 8
    for (int kk = 0; kk < 64; kk++) {
        float z[4], w[4];
#pragma unroll
        for (int i = 0; i < 4; i++) z[i] = Zs[4 * ty + i][kk];
#pragma unroll
        for (int j = 0; j < 4; j++) w[j] = Ws[tx + 32 * j][kk];
#pragma unroll
        for (int i = 0; i < 4; i++)
#pragma unroll
            for (int j = 0; j < 4; j++)
                acc[i][j] = fmaf(z[i], w[j], acc[i][j]);
    }

    float* dst = g_gpart + ((size_t)ks * 32 + 4 * ty) * 2048 + nBase + tx;
#pragma unroll
    for (int i = 0; i < 4; i++)
#pragma unroll
        for (int j = 0; j < 4; j++)
            dst[(size_t)i * 2048 + 32 * j] = acc[i][j];
}

// ---------------- fused cell + LayerNorm ; grid BB ----------------
__global__ __launch_bounds__(256) void cell_kernel(int t, const float* __restrict__ lnw,
                                                   const float* __restrict__ lnb)
{
    const int b = blockIdx.x, tid = threadIdx.x;
    const int warp = tid >> 5, lane = tid & 31;
    __shared__ float redS[8], redQ[8], mv[2];
    float hr[2];
    float sum = 0.f, ssq = 0.f;
    const float* Gx = g_Gx + (size_t)(b * TT + t) * 2048;

#pragma unroll
    for (int u = 0; u < 2; u++) {
        const int d = tid + u * 256;
        float gi = Gx[d], gf = Gx[512 + d], gg = Gx[1024 + d], go = Gx[1536 + d];
#pragma unroll
        for (int s = 0; s < 16; s++) {
            const float* P = g_gpart + ((size_t)s * 32 + b) * 2048;
            gi += P[d]; gf += P[512 + d]; gg += P[1024 + d]; go += P[1536 + d];
        }
        const float c_old = g_c[b * DH + d];
        const float cn = sigm(gf) * c_old + sigm(gi) * tanhf(gg);
        g_c[b * DH + d] = cn;
        const float h = sigm(go) * tanhf(cn);
        hr[u] = h; sum += h; ssq += h * h;
    }
#pragma unroll
    for (int o = 16; o; o >>= 1) {
        sum += __shfl_xor_sync(0xffffffffu, sum, o);
        ssq += __shfl_xor_sync(0xffffffffu, ssq, o);
    }
    if (lane == 0) { redS[warp] = sum; redQ[warp] = ssq; }
    __syncthreads();
    if (tid < 8) {
        float s = redS[tid], q = redQ[tid];
#pragma unroll
        for (int o = 4; o; o >>= 1) {
            s += __shfl_xor_sync(0x000000ffu, s, o);
            q += __shfl_xor_sync(0x000000ffu, q, o);
        }
        if (tid == 0) { mv[0] = s * (1.f / DH); mv[1] = q * (1.f / DH); }
    }
    __syncthreads();
    const float mu = mv[0];
    const float var = mv[1] - mu * mu;
    const float rstd = rsqrtf(var + 1e-5f);
#pragma unroll
    for (int u = 0; u < 2; u++) {
        const int d = tid + u * 256;
        const float h = (hr[u] - mu) * rstd * lnw[d] + lnb[d];
        g_z[b * 1024 + 512 + d] = h;
        g_hall[(size_t)(b * TT + t) * DH + d] = h;
    }
}

// ---------------- launch ----------------
extern "C" void kernel_launch(void* const* d_in, const int* in_sizes, int n_in,
                              void* d_out, int out_size)
{
    const float* patches = (const float*)d_in[0];
    const float* cls     = (const float*)d_in[1];
    const int*   tgt     = (const int*)  d_in[2];
    const float* emb     = (const float*)d_in[3];
    const float* kvW     = (const float*)d_in[4];
    const float* kvb     = (const float*)d_in[5];
    const float* ihW     = (const float*)d_in[6];
    const float* ihb     = (const float*)d_in[7];
    const float* icW     = (const float*)d_in[8];
    const float* icb     = (const float*)d_in[9];
    const float* aWh     = (const float*)d_in[10];
    const float* aWk     = (const float*)d_in[11];
    const float* av      = (const float*)d_in[12];
    const float* Wih     = (const float*)d_in[13];
    const float* Whh     = (const float*)d_in[14];
    const float* bih     = (const float*)d_in[15];
    const float* bhh     = (const float*)d_in[16];
    const float* lnw     = (const float*)d_in[17];
    const float* lnb     = (const float*)d_in[18];
    const float* outW    = (const float*)d_in[19];
    const float* outb    = (const float*)d_in[20];
    float* out = (float*)d_out;

    float *keys, *wk, *xseq, *Gx, *z, *c, *hall;
    cudaGetSymbolAddress((void**)&keys, g_keys);
    cudaGetSymbolAddress((void**)&wk,   g_wk);
    cudaGetSymbolAddress((void**)&xseq, g_xseq);
    cudaGetSymbolAddress((void**)&Gx,   g_Gx);
    cudaGetSymbolAddress((void**)&z,    g_z);
    cudaGetSymbolAddress((void**)&c,    g_c);
    cudaGetSymbolAddress((void**)&hall, g_hall);

    // pre-loop
    gather_x<<<(BB * TT * DH) / 256, 256>>>(tgt, emb);
    gemm_nt<<<dim3(4, 49), 256>>>(patches, 768, kvW, 768, kvb, nullptr, keys, 512, BB * NN, 512, 768);
    gemm_nt<<<dim3(4, 49), 256>>>(keys, 512, aWk, 512, nullptr, nullptr, wk, 512, BB * NN, 512, 512);
    gemm_nt<<<dim3(4, 1), 256>>>(cls, 768, ihW, 768, ihb, nullptr, z + 512, 1024, BB, 512, 768);
    gemm_nt<<<dim3(4, 1), 256>>>(cls, 768, icW, 768, icb, nullptr, c, 512, BB, 512, 768);
    gemm_nt<<<dim3(16, 32), 256>>>(xseq, 512, Wih, 1024, bih, bhh, Gx, 2048, BB * TT, 2048, 512);

    // sequential decode loop
    for (int t = 0; t < TT; t++) {
        hwh_kernel   <<<dim3(8, BB), 256>>>(aWh);
        scores_kernel<<<dim3(25, BB), 256>>>(av);
        softctx_kernel<<<BB, 256>>>();
        gates_kernel <<<dim3(16, 16), 256>>>(Wih, Whh);
        cell_kernel  <<<BB, 256>>>(t, lnw, lnb);
    }

    // deferred logits: [4096, 10000] = hall @ outW^T + outb
    gemm_nt<<<dim3(79, 32), 256>>>(hall, 512, outW, 512, outb, nullptr, out, VV, BB * TT, VV, 512);
}